// round 6
// baseline (speedup 1.0000x reference)
#include <cuda_runtime.h>
#include <cstdint>
#include <cstddef>

// ---------------- constants ----------------
// segments:
//  L1  : seg = (m<<10) + (c<<7) + o   m in {0,1}, c = 128-col chunk 0..7, o = 0..127  -> 2048 segs, len 128
//  W2  : 2048 + o  (128 segs, len 512)
//  W3  : 2176 + o  ( 64 segs, len 128)
//  Wout: 2240 + o  (128 segs, len  64)
#define NSEG       2368
#define SEG_W2     2048
#define SEG_W3     2176
#define SEG_WOUT   2240
#define LIST_MAX   360448
#define LIST_CAP   16384
#define ACTS       1.3333333730697632f

#define THREADS    1024
#define GRID       256           // 32768 / 128 rows per block

// ---------------- device scratch ----------------
__device__ int   d_scale_bits[5];     // zero-init; atomicMax idempotent across replays
__device__ int   d_cnt[NSEG];
__device__ int   d_off[NSEG + 1];
__device__ __align__(16) unsigned short d_list[LIST_MAX];

// ---------------- prep 1: per-tensor max|w| ----------------
__global__ void prep_scale(const float* __restrict__ W1a, const float* __restrict__ W1b,
                           const float* __restrict__ W2,  const float* __restrict__ W3,
                           const float* __restrict__ Wout)
{
    __shared__ float red[8];
    int m = blockIdx.x >> 5;
    int part = blockIdx.x & 31;
    const float* W; int n;
    switch (m) {
        case 0: W = W1a;  n = 131072; break;
        case 1: W = W1b;  n = 131072; break;
        case 2: W = W2;   n = 65536;  break;
        case 3: W = W3;   n = 8192;   break;
        default: W = Wout; n = 8192;  break;
    }
    int chunk = n >> 5;
    int lo = part * chunk;
    float mx = 0.0f;
    for (int i = lo + threadIdx.x; i < lo + chunk; i += 256)
        mx = fmaxf(mx, fabsf(W[i]));
    #pragma unroll
    for (int o = 16; o; o >>= 1) mx = fmaxf(mx, __shfl_xor_sync(0xffffffffu, mx, o));
    if ((threadIdx.x & 31) == 0) red[threadIdx.x >> 5] = mx;
    __syncthreads();
    if (threadIdx.x < 32) {
        float v = (threadIdx.x < 8) ? red[threadIdx.x] : 0.0f;
        #pragma unroll
        for (int o = 4; o; o >>= 1) v = fmaxf(v, __shfl_xor_sync(0xffffffffu, v, o));
        if (threadIdx.x == 0) atomicMax(&d_scale_bits[m], __float_as_int(v));
    }
}

// ---------------- segment decode ----------------
struct SegInfo { const float* rowp; int len; float s; bool l1; };

__device__ __forceinline__ SegInfo seg_decode(int seg,
    const float* W1a, const float* W1b, const float* W2,
    const float* W3, const float* Wout)
{
    SegInfo r;
    if (seg < SEG_W2) {
        int m = seg >> 10, rem = seg & 1023;
        int c = rem >> 7, o = rem & 127;
        r.rowp = (m ? W1b : W1a) + o * 1024 + c * 128;
        r.len = 128; r.s = __int_as_float(d_scale_bits[m]); r.l1 = true;
    } else if (seg < SEG_W3) {
        r.rowp = W2 + (seg - SEG_W2) * 512;
        r.len = 512; r.s = __int_as_float(d_scale_bits[2]); r.l1 = false;
    } else if (seg < SEG_WOUT) {
        r.rowp = W3 + (seg - SEG_W3) * 128;
        r.len = 128; r.s = __int_as_float(d_scale_bits[3]); r.l1 = false;
    } else {
        r.rowp = Wout + (seg - SEG_WOUT) * 64;
        r.len = 64; r.s = __int_as_float(d_scale_bits[4]); r.l1 = false;
    }
    return r;
}

// ---------------- prep 2: count nnz per segment (exact, no pad) ----------------
__global__ void prep_count(const float* __restrict__ W1a, const float* __restrict__ W1b,
                           const float* __restrict__ W2,  const float* __restrict__ W3,
                           const float* __restrict__ Wout)
{
    int lane = threadIdx.x & 31;
    int seg = blockIdx.x * 8 + (threadIdx.x >> 5);
    if (seg >= NSEG) return;
    SegInfo si = seg_decode(seg, W1a, W1b, W2, W3, Wout);
    int cnt = 0;
    for (int j0 = 0; j0 < si.len; j0 += 32) {
        float w = si.rowp[j0 + lane];
        float q = rintf(__fdiv_rn(w, si.s));
        unsigned bal = __ballot_sync(0xffffffffu, q != 0.0f);
        cnt += __popc(bal);
    }
    if (lane == 0) d_cnt[seg] = cnt;
}

// ---------------- prep 3: scan (redundant per block) + fill ----------------
// L1 entry    = (idx << 1) | neg          (idx < 128)
// other entry = (idx*36 << 1) | neg = idx*72 | neg  (byte offset into packed codes)
__global__ void prep_scanfill(const float* __restrict__ W1a, const float* __restrict__ W1b,
                              const float* __restrict__ W2,  const float* __restrict__ W3,
                              const float* __restrict__ Wout)
{
    __shared__ int s_off[NSEG + 1];
    __shared__ int warpsum[8];
    int tid = threadIdx.x;
    int lane = tid & 31, w = tid >> 5;

    // local exclusive scan of d_cnt: 256 threads x 10 = 2560 >= 2369
    {
        int base = tid * 10;
        int v[10]; int s = 0;
        #pragma unroll
        for (int k = 0; k < 10; k++) {
            int idx = base + k;
            int c = (idx < NSEG) ? d_cnt[idx] : 0;
            v[k] = s; s += c;
        }
        int incl = s;
        #pragma unroll
        for (int o = 1; o < 32; o <<= 1) {
            int t = __shfl_up_sync(0xffffffffu, incl, o);
            if (lane >= o) incl += t;
        }
        if (lane == 31) warpsum[w] = incl;
        __syncthreads();
        if (w == 0 && lane < 8) {
            int ws = warpsum[lane];
            #pragma unroll
            for (int o = 1; o < 8; o <<= 1) {
                int t = __shfl_up_sync(0xffu, ws, o);
                if (lane >= o) ws += t;
            }
            warpsum[lane] = ws;
        }
        __syncthreads();
        int excl = incl - s + (w ? warpsum[w - 1] : 0);
        #pragma unroll
        for (int k = 0; k < 10; k++) {
            int idx = base + k;
            if (idx <= NSEG) s_off[idx] = excl + v[k];
        }
        __syncthreads();
    }

    if (blockIdx.x == 0)
        for (int i = tid; i <= NSEG; i += 256) d_off[i] = s_off[i];

    for (int seg = blockIdx.x * 8 + w; seg < NSEG; seg += gridDim.x * 8) {
        SegInfo si = seg_decode(seg, W1a, W1b, W2, W3, Wout);
        int base = s_off[seg];
        for (int j0 = 0; j0 < si.len; j0 += 32) {
            float wv = si.rowp[j0 + lane];
            float q = rintf(__fdiv_rn(wv, si.s));
            bool nz = (q != 0.0f);
            unsigned bal = __ballot_sync(0xffffffffu, nz);
            if (nz) {
                int pos = base + __popc(bal & ((1u << lane) - 1u));
                int idx = j0 + lane;
                int neg = (q < 0.0f) ? 1 : 0;
                int e = si.l1 ? ((idx << 1) | neg) : ((idx * 72) | neg);
                d_list[pos] = (unsigned short)e;
            }
            base += __popc(bal);
        }
    }
}

// ---------------- main kernel ----------------
// smem (bytes):
//  XS0  @ 0       : 128 cols * 132 rows * 4 = 67584  (x tile [col][row], word stride 132)
//  XS1  @ 67584   : 67584                       (end 135168)
//  H1   @ 135168  : 512*36 = 18432  (packed codes: [idx][lane], 4 rows/byte) (end 153600)
//  H2   @ 153600  : 128*36 =  4608  (end 158208)
//  H3   @ 158208  :  64*36 =  2304  (end 160512)
//  OFF  @ 160512  : 2369*4 =  9476  (end 169988)
//  LIST @ 169988  : 16384*2 = 32768 (end 202756)
//  OUTS aliases XS0 ( [o][row], 128*132*4 = 67584 )
#define SMEM_BYTES 202756

__device__ __forceinline__ float quant_relu_q(float y) {
    float qv = rintf(__fdiv_rn(y, ACTS));
    return fminf(fmaxf(qv, 0.0f), 3.0f);
}

template<bool USE_SM>
__device__ __forceinline__ void mlp_body(
    unsigned char* smem,
    const float* __restrict__ x,
    const float* __restrict__ b1a, const float* __restrict__ b1b,
    const float* __restrict__ b2,  const float* __restrict__ b3,
    float* __restrict__ out, int row0)
{
    float* xs0 = (float*)(smem);
    float* xs1 = (float*)(smem + 67584);
    unsigned char* h1s = smem + 135168;
    unsigned char* h2s = smem + 153600;
    unsigned char* h3s = smem + 158208;
    int* s_off = (int*)(smem + 160512);
    const unsigned short* lst = USE_SM ? (const unsigned short*)(smem + 169988)
                                       : (const unsigned short*)d_list;
    float* outs = (float*)(smem);     // alias XS0, layout [o][row] stride 132

    const int tid  = threadIdx.x;
    const int lane = tid & 31;
    const int g    = tid >> 5;        // warp 0..31
    // staging: thread -> row (tid&127), col4 base (tid>>7)
    const int srow = tid & 127;
    const int sc4  = tid >> 7;
    const float* xrow = x + (size_t)(row0 + srow) * 4096 + (sc4 << 2);

    const float sc1a = __int_as_float(d_scale_bits[0]);
    const float sc1b = __int_as_float(d_scale_bits[1]);
    const float s2   = __int_as_float(d_scale_bits[2]);
    const float s3   = __int_as_float(d_scale_bits[3]);
    const float s4   = __int_as_float(d_scale_bits[4]);

    float4 pf[4];

    // preload tile 0 (cols 0..127)
    #pragma unroll
    for (int k = 0; k < 4; k++) pf[k] = __ldcs((const float4*)(xrow + (k << 5)));
    #pragma unroll
    for (int k = 0; k < 4; k++) {
        int cb = (sc4 + (k << 3)) << 2;      // starting col of this float4
        xs0[(cb + 0) * 132 + srow] = pf[k].x;
        xs0[(cb + 1) * 132 + srow] = pf[k].y;
        xs0[(cb + 2) * 132 + srow] = pf[k].z;
        xs0[(cb + 3) * 132 + srow] = pf[k].w;
    }
    __syncthreads();
    // issue LDGs for tile 1
    #pragma unroll
    for (int k = 0; k < 4; k++) pf[k] = __ldcs((const float4*)(xrow + 128 + (k << 5)));

    float a0[4], a1[4], a2[4], a3[4];
    #pragma unroll
    for (int j = 0; j < 4; j++) { a0[j] = a1[j] = a2[j] = a3[j] = 0.0f; }

    // ---- layer 1: 32 tiles of [128 rows x 128 cols] ----
    for (int t = 0; t < 32; ++t) {
        const int branch = t >> 3, c = t & 7, m = branch & 1;
        const float4* cur4 = (const float4*)((t & 1) ? xs1 : xs0);
        const float sc = m ? sc1b : sc1a;

        #pragma unroll
        for (int j = 0; j < 4; j++) {
            int o = (g << 2) + j;
            int seg = (m << 10) + (c << 7) + o;
            int p0 = s_off[seg], p1 = s_off[seg + 1];
            float t0 = a0[j], t1 = a1[j], t2 = a2[j], t3 = a3[j];
            for (int p = p0; p < p1; ++p) {
                unsigned e = lst[p];
                float4 v = cur4[(e >> 1) * 33 + lane];   // rows 4*lane..4*lane+3
                float w = (e & 1u) ? -sc : sc;
                t0 = fmaf(w, v.x, t0); t1 = fmaf(w, v.y, t1);
                t2 = fmaf(w, v.z, t2); t3 = fmaf(w, v.w, t3);
            }
            a0[j] = t0; a1[j] = t1; a2[j] = t2; a3[j] = t3;
        }

        if (c == 7) {     // branch complete: quantize 4 outputs x 4 rows -> packed byte
            const float* bb = m ? b1b : b1a;
            #pragma unroll
            for (int j = 0; j < 4; j++) {
                int o = (g << 2) + j;
                float bv = bb[o];
                unsigned c0 = (unsigned)(int)quant_relu_q(a0[j] + bv);
                unsigned c1 = (unsigned)(int)quant_relu_q(a1[j] + bv);
                unsigned c2 = (unsigned)(int)quant_relu_q(a2[j] + bv);
                unsigned c3 = (unsigned)(int)quant_relu_q(a3[j] + bv);
                h1s[(branch * 128 + o) * 36 + lane] =
                    (unsigned char)(c0 | (c1 << 2) | (c2 << 4) | (c3 << 6));
                a0[j] = a1[j] = a2[j] = a3[j] = 0.0f;
            }
        }

        if (t + 1 < 32) {
            float* nxt = (t & 1) ? xs0 : xs1;
            #pragma unroll
            for (int k = 0; k < 4; k++) {
                int cb = (sc4 + (k << 3)) << 2;
                nxt[(cb + 0) * 132 + srow] = pf[k].x;
                nxt[(cb + 1) * 132 + srow] = pf[k].y;
                nxt[(cb + 2) * 132 + srow] = pf[k].z;
                nxt[(cb + 3) * 132 + srow] = pf[k].w;
            }
            __syncthreads();
            if (t + 2 < 32) {
                const float* xb = xrow + (t + 2) * 128;
                #pragma unroll
                for (int k = 0; k < 4; k++)
                    pf[k] = __ldcs((const float4*)(xb + (k << 5)));
            }
        }
    }
    __syncthreads();

    // ---- layer 2: 512 -> 128 ----
    {
        const unsigned char* hr = h1s + lane;
        #pragma unroll
        for (int j = 0; j < 4; j++) {
            int o = (g << 2) + j;
            int seg = SEG_W2 + o;
            int p0 = s_off[seg], p1 = s_off[seg + 1];
            int i0 = 0, i1 = 0, i2 = 0, i3 = 0;
            for (int p = p0; p < p1; ++p) {
                unsigned e = lst[p];
                int b = hr[e >> 1];
                int c0 = b & 3, c1 = (b >> 2) & 3, c2 = (b >> 4) & 3, c3 = (b >> 6) & 3;
                if (e & 1u) { i0 -= c0; i1 -= c1; i2 -= c2; i3 -= c3; }
                else        { i0 += c0; i1 += c1; i2 += c2; i3 += c3; }
            }
            float bv = b2[o];
            unsigned q0 = (unsigned)(int)quant_relu_q(fmaf((float)i0 * ACTS, s2, bv));
            unsigned q1 = (unsigned)(int)quant_relu_q(fmaf((float)i1 * ACTS, s2, bv));
            unsigned q2 = (unsigned)(int)quant_relu_q(fmaf((float)i2 * ACTS, s2, bv));
            unsigned q3 = (unsigned)(int)quant_relu_q(fmaf((float)i3 * ACTS, s2, bv));
            h2s[o * 36 + lane] = (unsigned char)(q0 | (q1 << 2) | (q2 << 4) | (q3 << 6));
        }
    }
    __syncthreads();

    // ---- layer 3: 128 -> 64 ----
    {
        const unsigned char* hr = h2s + lane;
        #pragma unroll
        for (int j = 0; j < 2; j++) {
            int o = (g << 1) + j;
            int seg = SEG_W3 + o;
            int p0 = s_off[seg], p1 = s_off[seg + 1];
            int i0 = 0, i1 = 0, i2 = 0, i3 = 0;
            for (int p = p0; p < p1; ++p) {
                unsigned e = lst[p];
                int b = hr[e >> 1];
                int c0 = b & 3, c1 = (b >> 2) & 3, c2 = (b >> 4) & 3, c3 = (b >> 6) & 3;
                if (e & 1u) { i0 -= c0; i1 -= c1; i2 -= c2; i3 -= c3; }
                else        { i0 += c0; i1 += c1; i2 += c2; i3 += c3; }
            }
            float bv = b3[o];
            unsigned q0 = (unsigned)(int)quant_relu_q(fmaf((float)i0 * ACTS, s3, bv));
            unsigned q1 = (unsigned)(int)quant_relu_q(fmaf((float)i1 * ACTS, s3, bv));
            unsigned q2 = (unsigned)(int)quant_relu_q(fmaf((float)i2 * ACTS, s3, bv));
            unsigned q3 = (unsigned)(int)quant_relu_q(fmaf((float)i3 * ACTS, s3, bv));
            h3s[o * 36 + lane] = (unsigned char)(q0 | (q1 << 2) | (q2 << 4) | (q3 << 6));
        }
    }
    __syncthreads();

    // ---- output layer: 64 -> 128, no bias; write [o][row] with STS.128 ----
    {
        const unsigned char* hr = h3s + lane;
        #pragma unroll
        for (int j = 0; j < 4; j++) {
            int o = (g << 2) + j;
            int seg = SEG_WOUT + o;
            int p0 = s_off[seg], p1 = s_off[seg + 1];
            int i0 = 0, i1 = 0, i2 = 0, i3 = 0;
            for (int p = p0; p < p1; ++p) {
                unsigned e = lst[p];
                int b = hr[e >> 1];
                int c0 = b & 3, c1 = (b >> 2) & 3, c2 = (b >> 4) & 3, c3 = (b >> 6) & 3;
                if (e & 1u) { i0 -= c0; i1 -= c1; i2 -= c2; i3 -= c3; }
                else        { i0 += c0; i1 += c1; i2 += c2; i3 += c3; }
            }
            float4 r;
            r.x = ((float)i0 * ACTS) * s4;
            r.y = ((float)i1 * ACTS) * s4;
            r.z = ((float)i2 * ACTS) * s4;
            r.w = ((float)i3 * ACTS) * s4;
            ((float4*)outs)[o * 33 + lane] = r;   // rows 4*lane..4*lane+3 of output o
        }
    }
    __syncthreads();

    // ---- final store: warp g covers rows 4g..4g+3 ----
    {
        int row = (g << 2) + (lane >> 3);
        int ob = (lane & 7) << 2;
        float* orow = out + (size_t)(row0 + row) * 128;
        #pragma unroll
        for (int i = 0; i < 4; i++) {
            int o = ob + (i << 5);
            float4 v;
            v.x = outs[(o + 0) * 132 + row];
            v.y = outs[(o + 1) * 132 + row];
            v.z = outs[(o + 2) * 132 + row];
            v.w = outs[(o + 3) * 132 + row];
            *(float4*)(orow + o) = v;
        }
    }
}

__global__ void __launch_bounds__(THREADS, 1) mlp_main(
    const float* __restrict__ x,
    const float* __restrict__ b1a, const float* __restrict__ b1b,
    const float* __restrict__ b2,  const float* __restrict__ b3,
    float* __restrict__ out)
{
    extern __shared__ unsigned char smem[];
    int* s_off = (int*)(smem + 160512);
    unsigned int* s_list = (unsigned int*)(smem + 169988);

    const int tid = threadIdx.x;
    const int row0 = blockIdx.x << 7;

    for (int i = tid; i <= NSEG; i += THREADS) s_off[i] = d_off[i];
    const int total = d_off[NSEG];
    const bool use_sm = (total <= LIST_CAP);
    if (use_sm) {
        const unsigned int* src = (const unsigned int*)d_list;
        int n32 = (total + 1) >> 1;
        for (int i = tid; i < n32; i += THREADS) s_list[i] = src[i];
    }
    __syncthreads();

    if (use_sm)
        mlp_body<true>(smem, x, b1a, b1b, b2, b3, out, row0);
    else
        mlp_body<false>(smem, x, b1a, b1b, b2, b3, out, row0);
}

// ---------------- launch ----------------
extern "C" void kernel_launch(void* const* d_in, const int* in_sizes, int n_in,
                              void* d_out, int out_size)
{
    const float* x    = (const float*)d_in[0];
    const float* W1a  = (const float*)d_in[1];
    const float* b1a  = (const float*)d_in[2];
    const float* W1b  = (const float*)d_in[3];
    const float* b1b  = (const float*)d_in[4];
    const float* W2   = (const float*)d_in[5];
    const float* b2   = (const float*)d_in[6];
    const float* W3   = (const float*)d_in[7];
    const float* b3   = (const float*)d_in[8];
    const float* Wout = (const float*)d_in[9];
    float* out = (float*)d_out;

    prep_scale<<<160, 256>>>(W1a, W1b, W2, W3, Wout);
    prep_count<<<NSEG / 8, 256>>>(W1a, W1b, W2, W3, Wout);
    prep_scanfill<<<148, 256>>>(W1a, W1b, W2, W3, Wout);

    cudaFuncSetAttribute(mlp_main, cudaFuncAttributeMaxDynamicSharedMemorySize, SMEM_BYTES);
    mlp_main<<<GRID, THREADS, SMEM_BYTES>>>(x, b1a, b1b, b2, b3, out);
}

// round 7
// speedup vs baseline: 1.0003x; 1.0003x over previous
#include <cuda_runtime.h>
#include <cstdint>
#include <cstddef>

// ---------------- constants ----------------
// segments:
//  L1  : seg = (m<<10) + (c<<7) + o   m in {0,1}, c = 128-col chunk 0..7, o = 0..127  -> 2048 segs, len 128
//  W2  : 2048 + o  (128 segs, len 512)
//  W3  : 2176 + o  ( 64 segs, len 128)
//  Wout: 2240 + o  (128 segs, len  64)
#define NSEG       2368
#define SEG_W2     2048
#define SEG_W3     2176
#define SEG_WOUT   2240
#define LIST_MAX   360448
#define LIST_CAP   16384
#define ACTS       1.3333333730697632f

#define THREADS    1024
#define GRID       256           // 32768 / 128 rows per block

// ---------------- device scratch ----------------
__device__ int   d_scale_bits[5];     // zero-init; atomicMax idempotent across replays
__device__ int   d_cnt[NSEG];
__device__ int   d_off[NSEG + 1];
__device__ __align__(16) unsigned short d_list[LIST_MAX];

// ---------------- prep 1: per-tensor max|w| ----------------
__global__ void prep_scale(const float* __restrict__ W1a, const float* __restrict__ W1b,
                           const float* __restrict__ W2,  const float* __restrict__ W3,
                           const float* __restrict__ Wout)
{
    __shared__ float red[8];
    int m = blockIdx.x >> 5;
    int part = blockIdx.x & 31;
    const float* W; int n;
    switch (m) {
        case 0: W = W1a;  n = 131072; break;
        case 1: W = W1b;  n = 131072; break;
        case 2: W = W2;   n = 65536;  break;
        case 3: W = W3;   n = 8192;   break;
        default: W = Wout; n = 8192;  break;
    }
    int chunk = n >> 5;
    int lo = part * chunk;
    float mx = 0.0f;
    for (int i = lo + threadIdx.x; i < lo + chunk; i += 256)
        mx = fmaxf(mx, fabsf(W[i]));
    #pragma unroll
    for (int o = 16; o; o >>= 1) mx = fmaxf(mx, __shfl_xor_sync(0xffffffffu, mx, o));
    if ((threadIdx.x & 31) == 0) red[threadIdx.x >> 5] = mx;
    __syncthreads();
    if (threadIdx.x < 32) {
        float v = (threadIdx.x < 8) ? red[threadIdx.x] : 0.0f;
        #pragma unroll
        for (int o = 4; o; o >>= 1) v = fmaxf(v, __shfl_xor_sync(0xffffffffu, v, o));
        if (threadIdx.x == 0) atomicMax(&d_scale_bits[m], __float_as_int(v));
    }
}

// ---------------- segment decode ----------------
struct SegInfo { const float* rowp; int len; float s; bool l1; };

__device__ __forceinline__ SegInfo seg_decode(int seg,
    const float* W1a, const float* W1b, const float* W2,
    const float* W3, const float* Wout)
{
    SegInfo r;
    if (seg < SEG_W2) {
        int m = seg >> 10, rem = seg & 1023;
        int c = rem >> 7, o = rem & 127;
        r.rowp = (m ? W1b : W1a) + o * 1024 + c * 128;
        r.len = 128; r.s = __int_as_float(d_scale_bits[m]); r.l1 = true;
    } else if (seg < SEG_W3) {
        r.rowp = W2 + (seg - SEG_W2) * 512;
        r.len = 512; r.s = __int_as_float(d_scale_bits[2]); r.l1 = false;
    } else if (seg < SEG_WOUT) {
        r.rowp = W3 + (seg - SEG_W3) * 128;
        r.len = 128; r.s = __int_as_float(d_scale_bits[3]); r.l1 = false;
    } else {
        r.rowp = Wout + (seg - SEG_WOUT) * 64;
        r.len = 64; r.s = __int_as_float(d_scale_bits[4]); r.l1 = false;
    }
    return r;
}

// ---------------- prep 2: count nnz per segment (exact, no pad) ----------------
__global__ void prep_count(const float* __restrict__ W1a, const float* __restrict__ W1b,
                           const float* __restrict__ W2,  const float* __restrict__ W3,
                           const float* __restrict__ Wout)
{
    int lane = threadIdx.x & 31;
    int seg = blockIdx.x * 8 + (threadIdx.x >> 5);
    if (seg >= NSEG) return;
    SegInfo si = seg_decode(seg, W1a, W1b, W2, W3, Wout);
    int cnt = 0;
    for (int j0 = 0; j0 < si.len; j0 += 32) {
        float w = si.rowp[j0 + lane];
        float q = rintf(__fdiv_rn(w, si.s));
        unsigned bal = __ballot_sync(0xffffffffu, q != 0.0f);
        cnt += __popc(bal);
    }
    if (lane == 0) d_cnt[seg] = cnt;
}

// ---------------- prep 3: scan (redundant per block) + fill ----------------
// L1 entry    = (idx << 1) | neg          (idx < 128)
// other entry = (idx*36 << 1) | neg = idx*72 | neg  (byte offset into packed codes)
__global__ void prep_scanfill(const float* __restrict__ W1a, const float* __restrict__ W1b,
                              const float* __restrict__ W2,  const float* __restrict__ W3,
                              const float* __restrict__ Wout)
{
    __shared__ int s_off[NSEG + 1];
    __shared__ int warpsum[8];
    int tid = threadIdx.x;
    int lane = tid & 31, w = tid >> 5;

    // local exclusive scan of d_cnt: 256 threads x 10 = 2560 >= 2369
    {
        int base = tid * 10;
        int v[10]; int s = 0;
        #pragma unroll
        for (int k = 0; k < 10; k++) {
            int idx = base + k;
            int c = (idx < NSEG) ? d_cnt[idx] : 0;
            v[k] = s; s += c;
        }
        int incl = s;
        #pragma unroll
        for (int o = 1; o < 32; o <<= 1) {
            int t = __shfl_up_sync(0xffffffffu, incl, o);
            if (lane >= o) incl += t;
        }
        if (lane == 31) warpsum[w] = incl;
        __syncthreads();
        if (w == 0 && lane < 8) {
            int ws = warpsum[lane];
            #pragma unroll
            for (int o = 1; o < 8; o <<= 1) {
                int t = __shfl_up_sync(0xffu, ws, o);
                if (lane >= o) ws += t;
            }
            warpsum[lane] = ws;
        }
        __syncthreads();
        int excl = incl - s + (w ? warpsum[w - 1] : 0);
        #pragma unroll
        for (int k = 0; k < 10; k++) {
            int idx = base + k;
            if (idx <= NSEG) s_off[idx] = excl + v[k];
        }
        __syncthreads();
    }

    if (blockIdx.x == 0)
        for (int i = tid; i <= NSEG; i += 256) d_off[i] = s_off[i];

    for (int seg = blockIdx.x * 8 + w; seg < NSEG; seg += gridDim.x * 8) {
        SegInfo si = seg_decode(seg, W1a, W1b, W2, W3, Wout);
        int base = s_off[seg];
        for (int j0 = 0; j0 < si.len; j0 += 32) {
            float wv = si.rowp[j0 + lane];
            float q = rintf(__fdiv_rn(wv, si.s));
            bool nz = (q != 0.0f);
            unsigned bal = __ballot_sync(0xffffffffu, nz);
            if (nz) {
                int pos = base + __popc(bal & ((1u << lane) - 1u));
                int idx = j0 + lane;
                int neg = (q < 0.0f) ? 1 : 0;
                int e = si.l1 ? ((idx << 1) | neg) : ((idx * 72) | neg);
                d_list[pos] = (unsigned short)e;
            }
            base += __popc(bal);
        }
    }
}

// ---------------- main kernel ----------------
// smem (bytes):
//  XS0  @ 0       : 128 cols * 132 rows * 4 = 67584  (x tile [col][row], word stride 132)
//  XS1  @ 67584   : 67584                       (end 135168)
//  H1   @ 135168  : 512*36 = 18432  (packed codes: [idx][lane], 4 rows/byte) (end 153600)
//  H2   @ 153600  : 128*36 =  4608  (end 158208)
//  H3   @ 158208  :  64*36 =  2304  (end 160512)
//  OFF  @ 160512  : 2369*4 =  9476  (end 169988)
//  LIST @ 169988  : 16384*2 = 32768 (end 202756)
//  OUTS aliases XS0 ( [o][row], 128*132*4 = 67584 )
#define SMEM_BYTES 202756

__device__ __forceinline__ float quant_relu_q(float y) {
    float qv = rintf(__fdiv_rn(y, ACTS));
    return fminf(fmaxf(qv, 0.0f), 3.0f);
}

template<bool USE_SM>
__device__ __forceinline__ void mlp_body(
    unsigned char* smem,
    const float* __restrict__ x,
    const float* __restrict__ b1a, const float* __restrict__ b1b,
    const float* __restrict__ b2,  const float* __restrict__ b3,
    float* __restrict__ out, int row0)
{
    float* xs0 = (float*)(smem);
    float* xs1 = (float*)(smem + 67584);
    unsigned char* h1s = smem + 135168;
    unsigned char* h2s = smem + 153600;
    unsigned char* h3s = smem + 158208;
    int* s_off = (int*)(smem + 160512);
    const unsigned short* lst = USE_SM ? (const unsigned short*)(smem + 169988)
                                       : (const unsigned short*)d_list;
    float* outs = (float*)(smem);     // alias XS0, layout [o][row] stride 132

    const int tid  = threadIdx.x;
    const int lane = tid & 31;
    const int g    = tid >> 5;        // warp 0..31
    // staging: thread -> row (tid&127), col4 base (tid>>7)
    const int srow = tid & 127;
    const int sc4  = tid >> 7;
    const float* xrow = x + (size_t)(row0 + srow) * 4096 + (sc4 << 2);

    const float sc1a = __int_as_float(d_scale_bits[0]);
    const float sc1b = __int_as_float(d_scale_bits[1]);
    const float s2   = __int_as_float(d_scale_bits[2]);
    const float s3   = __int_as_float(d_scale_bits[3]);
    const float s4   = __int_as_float(d_scale_bits[4]);

    float4 pf[4];

    // preload tile 0 (cols 0..127)
    #pragma unroll
    for (int k = 0; k < 4; k++) pf[k] = __ldcs((const float4*)(xrow + (k << 5)));
    #pragma unroll
    for (int k = 0; k < 4; k++) {
        int cb = (sc4 + (k << 3)) << 2;      // starting col of this float4
        xs0[(cb + 0) * 132 + srow] = pf[k].x;
        xs0[(cb + 1) * 132 + srow] = pf[k].y;
        xs0[(cb + 2) * 132 + srow] = pf[k].z;
        xs0[(cb + 3) * 132 + srow] = pf[k].w;
    }
    __syncthreads();
    // issue LDGs for tile 1
    #pragma unroll
    for (int k = 0; k < 4; k++) pf[k] = __ldcs((const float4*)(xrow + 128 + (k << 5)));

    float a0[4], a1[4], a2[4], a3[4];
    #pragma unroll
    for (int j = 0; j < 4; j++) { a0[j] = a1[j] = a2[j] = a3[j] = 0.0f; }

    // ---- layer 1: 32 tiles of [128 rows x 128 cols] ----
    for (int t = 0; t < 32; ++t) {
        const int branch = t >> 3, c = t & 7, m = branch & 1;
        const float4* cur4 = (const float4*)((t & 1) ? xs1 : xs0);
        const float sc = m ? sc1b : sc1a;

        #pragma unroll
        for (int j = 0; j < 4; j++) {
            int o = (g << 2) + j;
            int seg = (m << 10) + (c << 7) + o;
            int p0 = s_off[seg], p1 = s_off[seg + 1];
            float t0 = a0[j], t1 = a1[j], t2 = a2[j], t3 = a3[j];
            for (int p = p0; p < p1; ++p) {
                unsigned e = lst[p];
                float4 v = cur4[(e >> 1) * 33 + lane];   // rows 4*lane..4*lane+3
                float w = (e & 1u) ? -sc : sc;
                t0 = fmaf(w, v.x, t0); t1 = fmaf(w, v.y, t1);
                t2 = fmaf(w, v.z, t2); t3 = fmaf(w, v.w, t3);
            }
            a0[j] = t0; a1[j] = t1; a2[j] = t2; a3[j] = t3;
        }

        if (c == 7) {     // branch complete: quantize 4 outputs x 4 rows -> packed byte
            const float* bb = m ? b1b : b1a;
            #pragma unroll
            for (int j = 0; j < 4; j++) {
                int o = (g << 2) + j;
                float bv = bb[o];
                unsigned c0 = (unsigned)(int)quant_relu_q(a0[j] + bv);
                unsigned c1 = (unsigned)(int)quant_relu_q(a1[j] + bv);
                unsigned c2 = (unsigned)(int)quant_relu_q(a2[j] + bv);
                unsigned c3 = (unsigned)(int)quant_relu_q(a3[j] + bv);
                h1s[(branch * 128 + o) * 36 + lane] =
                    (unsigned char)(c0 | (c1 << 2) | (c2 << 4) | (c3 << 6));
                a0[j] = a1[j] = a2[j] = a3[j] = 0.0f;
            }
        }

        if (t + 1 < 32) {
            float* nxt = (t & 1) ? xs0 : xs1;
            #pragma unroll
            for (int k = 0; k < 4; k++) {
                int cb = (sc4 + (k << 3)) << 2;
                nxt[(cb + 0) * 132 + srow] = pf[k].x;
                nxt[(cb + 1) * 132 + srow] = pf[k].y;
                nxt[(cb + 2) * 132 + srow] = pf[k].z;
                nxt[(cb + 3) * 132 + srow] = pf[k].w;
            }
            __syncthreads();
            if (t + 2 < 32) {
                const float* xb = xrow + (t + 2) * 128;
                #pragma unroll
                for (int k = 0; k < 4; k++)
                    pf[k] = __ldcs((const float4*)(xb + (k << 5)));
            }
        }
    }
    __syncthreads();

    // ---- layer 2: 512 -> 128 ----
    {
        const unsigned char* hr = h1s + lane;
        #pragma unroll
        for (int j = 0; j < 4; j++) {
            int o = (g << 2) + j;
            int seg = SEG_W2 + o;
            int p0 = s_off[seg], p1 = s_off[seg + 1];
            int i0 = 0, i1 = 0, i2 = 0, i3 = 0;
            for (int p = p0; p < p1; ++p) {
                unsigned e = lst[p];
                int b = hr[e >> 1];
                int c0 = b & 3, c1 = (b >> 2) & 3, c2 = (b >> 4) & 3, c3 = (b >> 6) & 3;
                if (e & 1u) { i0 -= c0; i1 -= c1; i2 -= c2; i3 -= c3; }
                else        { i0 += c0; i1 += c1; i2 += c2; i3 += c3; }
            }
            float bv = b2[o];
            unsigned q0 = (unsigned)(int)quant_relu_q(fmaf((float)i0 * ACTS, s2, bv));
            unsigned q1 = (unsigned)(int)quant_relu_q(fmaf((float)i1 * ACTS, s2, bv));
            unsigned q2 = (unsigned)(int)quant_relu_q(fmaf((float)i2 * ACTS, s2, bv));
            unsigned q3 = (unsigned)(int)quant_relu_q(fmaf((float)i3 * ACTS, s2, bv));
            h2s[o * 36 + lane] = (unsigned char)(q0 | (q1 << 2) | (q2 << 4) | (q3 << 6));
        }
    }
    __syncthreads();

    // ---- layer 3: 128 -> 64 ----
    {
        const unsigned char* hr = h2s + lane;
        #pragma unroll
        for (int j = 0; j < 2; j++) {
            int o = (g << 1) + j;
            int seg = SEG_W3 + o;
            int p0 = s_off[seg], p1 = s_off[seg + 1];
            int i0 = 0, i1 = 0, i2 = 0, i3 = 0;
            for (int p = p0; p < p1; ++p) {
                unsigned e = lst[p];
                int b = hr[e >> 1];
                int c0 = b & 3, c1 = (b >> 2) & 3, c2 = (b >> 4) & 3, c3 = (b >> 6) & 3;
                if (e & 1u) { i0 -= c0; i1 -= c1; i2 -= c2; i3 -= c3; }
                else        { i0 += c0; i1 += c1; i2 += c2; i3 += c3; }
            }
            float bv = b3[o];
            unsigned q0 = (unsigned)(int)quant_relu_q(fmaf((float)i0 * ACTS, s3, bv));
            unsigned q1 = (unsigned)(int)quant_relu_q(fmaf((float)i1 * ACTS, s3, bv));
            unsigned q2 = (unsigned)(int)quant_relu_q(fmaf((float)i2 * ACTS, s3, bv));
            unsigned q3 = (unsigned)(int)quant_relu_q(fmaf((float)i3 * ACTS, s3, bv));
            h3s[o * 36 + lane] = (unsigned char)(q0 | (q1 << 2) | (q2 << 4) | (q3 << 6));
        }
    }
    __syncthreads();

    // ---- output layer: 64 -> 128, no bias; write [o][row] with STS.128 ----
    {
        const unsigned char* hr = h3s + lane;
        #pragma unroll
        for (int j = 0; j < 4; j++) {
            int o = (g << 2) + j;
            int seg = SEG_WOUT + o;
            int p0 = s_off[seg], p1 = s_off[seg + 1];
            int i0 = 0, i1 = 0, i2 = 0, i3 = 0;
            for (int p = p0; p < p1; ++p) {
                unsigned e = lst[p];
                int b = hr[e >> 1];
                int c0 = b & 3, c1 = (b >> 2) & 3, c2 = (b >> 4) & 3, c3 = (b >> 6) & 3;
                if (e & 1u) { i0 -= c0; i1 -= c1; i2 -= c2; i3 -= c3; }
                else        { i0 += c0; i1 += c1; i2 += c2; i3 += c3; }
            }
            float4 r;
            r.x = ((float)i0 * ACTS) * s4;
            r.y = ((float)i1 * ACTS) * s4;
            r.z = ((float)i2 * ACTS) * s4;
            r.w = ((float)i3 * ACTS) * s4;
            ((float4*)outs)[o * 33 + lane] = r;   // rows 4*lane..4*lane+3 of output o
        }
    }
    __syncthreads();

    // ---- final store: warp g covers rows 4g..4g+3 ----
    {
        int row = (g << 2) + (lane >> 3);
        int ob = (lane & 7) << 2;
        float* orow = out + (size_t)(row0 + row) * 128;
        #pragma unroll
        for (int i = 0; i < 4; i++) {
            int o = ob + (i << 5);
            float4 v;
            v.x = outs[(o + 0) * 132 + row];
            v.y = outs[(o + 1) * 132 + row];
            v.z = outs[(o + 2) * 132 + row];
            v.w = outs[(o + 3) * 132 + row];
            *(float4*)(orow + o) = v;
        }
    }
}

__global__ void __launch_bounds__(THREADS, 1) mlp_main(
    const float* __restrict__ x,
    const float* __restrict__ b1a, const float* __restrict__ b1b,
    const float* __restrict__ b2,  const float* __restrict__ b3,
    float* __restrict__ out)
{
    extern __shared__ unsigned char smem[];
    int* s_off = (int*)(smem + 160512);
    unsigned int* s_list = (unsigned int*)(smem + 169988);

    const int tid = threadIdx.x;
    const int row0 = blockIdx.x << 7;

    for (int i = tid; i <= NSEG; i += THREADS) s_off[i] = d_off[i];
    const int total = d_off[NSEG];
    const bool use_sm = (total <= LIST_CAP);
    if (use_sm) {
        const unsigned int* src = (const unsigned int*)d_list;
        int n32 = (total + 1) >> 1;
        for (int i = tid; i < n32; i += THREADS) s_list[i] = src[i];
    }
    __syncthreads();

    if (use_sm)
        mlp_body<true>(smem, x, b1a, b1b, b2, b3, out, row0);
    else
        mlp_body<false>(smem, x, b1a, b1b, b2, b3, out, row0);
}

// ---------------- launch ----------------
extern "C" void kernel_launch(void* const* d_in, const int* in_sizes, int n_in,
                              void* d_out, int out_size)
{
    const float* x    = (const float*)d_in[0];
    const float* W1a  = (const float*)d_in[1];
    const float* b1a  = (const float*)d_in[2];
    const float* W1b  = (const float*)d_in[3];
    const float* b1b  = (const float*)d_in[4];
    const float* W2   = (const float*)d_in[5];
    const float* b2   = (const float*)d_in[6];
    const float* W3   = (const float*)d_in[7];
    const float* b3   = (const float*)d_in[8];
    const float* Wout = (const float*)d_in[9];
    float* out = (float*)d_out;

    prep_scale<<<160, 256>>>(W1a, W1b, W2, W3, Wout);
    prep_count<<<NSEG / 8, 256>>>(W1a, W1b, W2, W3, Wout);
    prep_scanfill<<<148, 256>>>(W1a, W1b, W2, W3, Wout);

    cudaFuncSetAttribute(mlp_main, cudaFuncAttributeMaxDynamicSharedMemorySize, SMEM_BYTES);
    mlp_main<<<GRID, THREADS, SMEM_BYTES>>>(x, b1a, b1b, b2, b3, out);
}